// round 6
// baseline (speedup 1.0000x reference)
#include <cuda_runtime.h>

// Problem constants (fixed by the reference)
#define BB 8
#define NT 256
#define WHD 21
#define PP 441          // WHD*WHD
#define SPITCH 23       // padded patch pitch
#define SPSZ (SPITCH * 23 + 8)   // +8 zero slack for row-chunk over-read at sc==5
#define IMW 1024
#define ITERS 20
#define NTHREADS 128
#define NWARPS 4

__global__ __launch_bounds__(NTHREADS, 14)
void mt_kernel(const float* __restrict__ track,
               const float* __restrict__ imgs,
               float* __restrict__ out)
{
    const int id = blockIdx.x;           // 0 .. B*NT-1
    const int b = id >> 8;               // id / NT (NT = 256)
    const int t = id & 255;

    const float* f0 = imgs + (size_t)b * 2 * IMW * IMW;   // frame 0 (H==W==1024)
    const float* f1 = f0 + (size_t)(IMW * IMW);           // frame 1

    __shared__ float sP[SPSZ];                       // zero-padded sampled patch
    __shared__ __align__(16) float sRed[5][NWARPS];  // per-warp partial sums

    const int tid  = threadIdx.x;
    const int lane = tid & 31;
    const int wid  = tid >> 5;

    // mapping: thread = (patch row si, 4-col chunk sc); 126 active threads
    const int si   = tid / 6;
    const int sc   = tid - si * 6;
    const int sj0  = sc * 4;
    const bool act = (si < WHD);
    const int sncols = (sc == 5) ? 1 : 4;            // col 20 only in last chunk
    const float gyv = -1.0f + 0.1f * (float)si;      // linspace(-1,1,21)[si]

    // per-thread shift state (all threads compute identically)
    float sx, sy;
    {
        const float SCALE = 21.0f / 1024.0f;   // exact in fp32
        sx = track[b * (NT * 2) + t * 2 + 0] / SCALE;
        sy = track[b * (NT * 2) + t * 2 + 1] / SCALE;
    }

    // zero padded patch (+slack); border & slack stay zero forever
    #pragma unroll
    for (int k = tid; k < SPSZ; k += NTHREADS) sP[k] = 0.0f;

    // row-shared bilinear: 4 samples along row si, cols sj0..sj0+3.
    // Exact reference clip-then-weight arithmetic; y-tuple computed ONCE.
    auto sample4 = [&](const float* __restrict__ f, float ssx, float ssy,
                       float* res) {
        float y  = (gyv + ssy) * 10.5f;          // WH*0.5
        float fy = floorf(y);
        float y0 = fminf(fmaxf(fy,        0.0f), 1023.0f);
        float y1 = fminf(fmaxf(fy + 1.0f, 0.0f), 1023.0f);
        float wy0 = y1 - y;                      // (y1 - y)
        float wy1 = y  - y0;                     // (y - y0)
        const float* r0 = f + (int)y0 * IMW;
        const float* r1 = f + (int)y1 * IMW;
        #pragma unroll
        for (int jj = 0; jj < 4; ++jj) {
            if (jj < sncols) {
                float gx = -1.0f + 0.1f * (float)(sj0 + jj);
                float x  = (gx + ssx) * 10.5f;
                float fx = floorf(x);
                float x0 = fminf(fmaxf(fx,        0.0f), 1023.0f);
                float x1 = fminf(fmaxf(fx + 1.0f, 0.0f), 1023.0f);
                float wx0 = x1 - x;
                float wx1 = x  - x0;
                int xi0 = (int)x0, xi1 = (int)x1;
                // wa=(y1-y)*(x1-x), wb=(y1-y)*(x-x0), wc=(y-y0)*(x1-x), wd=(y-y0)*(x-x0)
                res[jj] = (wy0 * wx0) * __ldg(r0 + xi0)
                        + (wy0 * wx1) * __ldg(r0 + xi1)
                        + (wy1 * wx0) * __ldg(r1 + xi0)
                        + (wy1 * wx1) * __ldg(r1 + xi1);
            }
        }
    };

    // 'second' (frame 1 at initial positions) — fixed for all iterations
    float second[4] = {0.f, 0.f, 0.f, 0.f};
    if (act) {
        sample4(f1, sx, sy, second);
        float* o1 = out + ((((size_t)b * 2) + 1) * NT + t) * PP + si * WHD + sj0;
        #pragma unroll
        for (int jj = 0; jj < 4; ++jj)
            if (jj < sncols) o1[jj] = second[jj];
    }

    __syncthreads();   // padded border zeros visible

    for (int it = 0; it < ITERS; ++it) {
        // ---- sample f0 directly (L1-cached gathers) into padded patch ----
        float o0[4];
        if (act) {
            sample4(f0, sx, sy, o0);
            #pragma unroll
            for (int jj = 0; jj < 4; ++jj)
                if (jj < sncols) sP[(si + 1) * SPITCH + sj0 + 1 + jj] = o0[jj];
        }
        __syncthreads();                       // sync A: patch visible

        // ---- row-chunk Sobel stencil + local accumulation ----
        float v0 = 0.f, v1 = 0.f, v2 = 0.f, v3 = 0.f, v4 = 0.f;
        if (act) {
            const int base = si * SPITCH + sj0;
            float e[6], d[6];
            #pragma unroll
            for (int cc = 0; cc < 6; ++cc) {
                float la = sP[base + cc];
                float lb = sP[base + SPITCH + cc];
                float lc = sP[base + 2 * SPITCH + cc];
                e[cc] = fmaf(2.0f, lb, la + lc);   // vertical [1,2,1]
                d[cc] = lc - la;                   // vertical [-1,0,1]
            }
            #pragma unroll
            for (int jj = 0; jj < 4; ++jj) {
                if (jj < sncols) {
                    float Ix = e[jj + 2] - e[jj];
                    float Iy = fmaf(2.0f, d[jj + 1], d[jj] + d[jj + 2]);
                    float It = second[jj] - o0[jj];
                    v0 = fmaf(Ix, Ix, v0);
                    v1 = fmaf(Iy, Iy, v1);
                    v2 = fmaf(Ix, Iy, v2);
                    v3 = fmaf(Ix, It, v3);
                    v4 = fmaf(Iy, It, v4);
                }
            }
        }

        // stage 1: warp reduce
        #pragma unroll
        for (int off = 16; off; off >>= 1) {
            v0 += __shfl_down_sync(0xffffffffu, v0, off);
            v1 += __shfl_down_sync(0xffffffffu, v1, off);
            v2 += __shfl_down_sync(0xffffffffu, v2, off);
            v3 += __shfl_down_sync(0xffffffffu, v3, off);
            v4 += __shfl_down_sync(0xffffffffu, v4, off);
        }
        if (lane == 0) {
            sRed[0][wid] = v0;
            sRed[1][wid] = v1;
            sRed[2][wid] = v2;
            sRed[3][wid] = v3;
            sRed[4][wid] = v4;
        }
        __syncthreads();                       // sync B: partials visible

        // stage 2: vectorized broadcast reads; every thread solves locally
        float4 q0 = *(const float4*)(&sRed[0][0]);
        float4 q1 = *(const float4*)(&sRed[1][0]);
        float4 q2 = *(const float4*)(&sRed[2][0]);
        float4 q3 = *(const float4*)(&sRed[3][0]);
        float4 q4 = *(const float4*)(&sRed[4][0]);
        float Ix2  = (q0.x + q0.y) + (q0.z + q0.w);
        float Iy2  = (q1.x + q1.y) + (q1.z + q1.w);
        float IxIy = (q2.x + q2.y) + (q2.z + q2.w);
        float IxIt = (q3.x + q3.y) + (q3.z + q3.w);
        float IyIt = (q4.x + q4.y) + (q4.z + q4.w);

        float det_inv = 1.0f / (Ix2 * Iy2 - IxIy * IxIy);
        float Vx = det_inv * (Iy2    * (-IxIt) + (-IxIy) * (-IyIt));
        float Vy = det_inv * ((-IxIy) * (-IxIt) + Ix2    * (-IyIt));
        sx = sx - Vx;
        sy = sy - Vy;
    }

    // final sample of frame 0 at converged positions
    if (act) {
        float o0[4];
        sample4(f0, sx, sy, o0);
        float* o0p = out + ((((size_t)b * 2) + 0) * NT + t) * PP + si * WHD + sj0;
        #pragma unroll
        for (int jj = 0; jj < 4; ++jj)
            if (jj < sncols) o0p[jj] = o0[jj];
    }
}

extern "C" void kernel_launch(void* const* d_in, const int* in_sizes, int n_in,
                              void* d_out, int out_size)
{
    // track_locs: 8*512 = 4096 floats; imgs: 8*2*1024*1024 floats.
    const float* track;
    const float* imgs;
    if (in_sizes[0] < in_sizes[1]) {
        track = (const float*)d_in[0];
        imgs  = (const float*)d_in[1];
    } else {
        track = (const float*)d_in[1];
        imgs  = (const float*)d_in[0];
    }
    float* out = (float*)d_out;
    mt_kernel<<<BB * NT, NTHREADS>>>(track, imgs, out);
}

// round 7
// speedup vs baseline: 1.0768x; 1.0768x over previous
#include <cuda_runtime.h>

// Problem constants (fixed by the reference)
#define BB 8
#define NT 256
#define WHD 21
#define PP 441          // WHD*WHD
#define SPITCH 23       // padded patch pitch
#define SPSZ (SPITCH * 23 + 8)   // +8 zero slack for row-chunk over-read at sc==5
#define WIN 24          // staged f0 window dim (covers exact 21px span + bilinear +1)
#define IMW 1024
#define ITERS 20
#define NTHREADS 128
#define NWARPS 4

__global__ __launch_bounds__(NTHREADS, 14)
void mt_kernel(const float* __restrict__ track,
               const float* __restrict__ imgs,
               float* __restrict__ out)
{
    const int id = blockIdx.x;           // 0 .. B*NT-1
    const int b = id >> 8;               // id / NT (NT = 256)
    const int t = id & 255;

    const float* f0 = imgs + (size_t)b * 2 * IMW * IMW;   // frame 0 (H==W==1024)
    const float* f1 = f0 + (size_t)(IMW * IMW);           // frame 1

    __shared__ float sW[WIN * WIN];                  // staged f0 window
    __shared__ float sP[SPSZ];                       // zero-padded sampled patch
    __shared__ __align__(16) float sRed[5][NWARPS];  // per-warp partial sums

    const int tid  = threadIdx.x;
    const int lane = tid & 31;
    const int wid  = tid >> 5;

    // mapping: thread = (patch row si, 4-col chunk sc); 126 active threads
    const int si   = tid / 6;
    const int sc   = tid - si * 6;
    const int sj0  = sc * 4;
    const bool act = (si < WHD);
    const int sncols = (sc == 5) ? 1 : 4;            // col 20 only in last chunk
    const float gyv = -1.0f + 0.1f * (float)si;      // linspace(-1,1,21)[si]

    // per-thread shift state (all threads compute identically)
    float sx, sy;
    {
        const float SCALE = 21.0f / 1024.0f;   // exact in fp32
        sx = track[b * (NT * 2) + t * 2 + 0] / SCALE;
        sy = track[b * (NT * 2) + t * 2 + 1] / SCALE;
    }

    // zero padded patch (+slack); border & slack stay zero forever
    #pragma unroll
    for (int k = tid; k < SPSZ; k += NTHREADS) sP[k] = 0.0f;

    // direct-gather bilinear for the once-only f1 'second' and final f0 sample
    // (exact reference clip-then-weight arithmetic; y-tuple shared across row)
    auto sample4G = [&](const float* __restrict__ f, float ssx, float ssy,
                        float* res) {
        float y  = (gyv + ssy) * 10.5f;          // WH*0.5
        float fy = floorf(y);
        float y0 = fminf(fmaxf(fy,        0.0f), 1023.0f);
        float y1 = fminf(fmaxf(fy + 1.0f, 0.0f), 1023.0f);
        float wy0 = y1 - y;
        float wy1 = y  - y0;
        const float* r0 = f + (int)y0 * IMW;
        const float* r1 = f + (int)y1 * IMW;
        #pragma unroll
        for (int jj = 0; jj < 4; ++jj) {
            if (jj < sncols) {
                float gx = -1.0f + 0.1f * (float)(sj0 + jj);
                float x  = (gx + ssx) * 10.5f;
                float fx = floorf(x);
                float x0 = fminf(fmaxf(fx,        0.0f), 1023.0f);
                float x1 = fminf(fmaxf(fx + 1.0f, 0.0f), 1023.0f);
                float wx0 = x1 - x;
                float wx1 = x  - x0;
                int xi0 = (int)x0, xi1 = (int)x1;
                res[jj] = (wy0 * wx0) * __ldg(r0 + xi0)
                        + (wy0 * wx1) * __ldg(r0 + xi1)
                        + (wy1 * wx0) * __ldg(r1 + xi0)
                        + (wy1 * wx1) * __ldg(r1 + xi1);
            }
        }
    };

    // 'second' (frame 1 at initial positions) — fixed for all iterations
    float second[4] = {0.f, 0.f, 0.f, 0.f};
    if (act) {
        sample4G(f1, sx, sy, second);
        float* o1 = out + ((((size_t)b * 2) + 1) * NT + t) * PP + si * WHD + sj0;
        #pragma unroll
        for (int jj = 0; jj < 4; ++jj)
            if (jj < sncols) o1[jj] = second[jj];
    }

    __syncthreads();   // padded border zeros visible

    for (int it = 0; it < ITERS; ++it) {
        // ---- window base (identical on all threads; index monotonicity => coverage)
        int cbase, rbase;
        {
            float xf = (-1.0f + sx) * 10.5f;   // x at j=0
            float yf = (-1.0f + sy) * 10.5f;   // y at i=0
            cbase = min(max((int)floorf(xf), 0), IMW - WIN);
            rbase = min(max((int)floorf(yf), 0), IMW - WIN);
        }

        // ---- stage 24x24 f0 window (576 coalesced LDGs) ----
        {
            const float* wsrc = f0 + rbase * IMW + cbase;
            #pragma unroll
            for (int k = 0; k < 5; ++k) {
                int idx = tid + k * NTHREADS;
                if (idx < WIN * WIN) {
                    int r = idx / WIN;
                    int c = idx - r * WIN;
                    sW[idx] = __ldg(wsrc + r * IMW + c);
                }
            }
        }
        __syncthreads();                       // sync W: window visible

        // ---- sample f0 from window; y-tuple once per thread ----
        float o0[4];
        if (act) {
            float y  = (gyv + sy) * 10.5f;
            float fy = floorf(y);
            float y0 = fminf(fmaxf(fy,        0.0f), 1023.0f);
            float y1 = fminf(fmaxf(fy + 1.0f, 0.0f), 1023.0f);
            float wy0 = y1 - y;
            float wy1 = y  - y0;
            const float* w0 = sW + ((int)y0 - rbase) * WIN - cbase;
            const float* w1 = sW + ((int)y1 - rbase) * WIN - cbase;
            #pragma unroll
            for (int jj = 0; jj < 4; ++jj) {
                if (jj < sncols) {
                    float gx = -1.0f + 0.1f * (float)(sj0 + jj);
                    float x  = (gx + sx) * 10.5f;
                    float fx = floorf(x);
                    float x0 = fminf(fmaxf(fx,        0.0f), 1023.0f);
                    float x1 = fminf(fmaxf(fx + 1.0f, 0.0f), 1023.0f);
                    float wx0 = x1 - x;
                    float wx1 = x  - x0;
                    int xi0 = (int)x0, xi1 = (int)x1;
                    o0[jj] = (wy0 * wx0) * w0[xi0]
                           + (wy0 * wx1) * w0[xi1]
                           + (wy1 * wx0) * w1[xi0]
                           + (wy1 * wx1) * w1[xi1];
                    sP[(si + 1) * SPITCH + sj0 + 1 + jj] = o0[jj];
                }
            }
        }
        __syncthreads();                       // sync A: patch visible

        // ---- row-chunk Sobel stencil + local accumulation ----
        float v0 = 0.f, v1 = 0.f, v2 = 0.f, v3 = 0.f, v4 = 0.f;
        if (act) {
            const int base = si * SPITCH + sj0;
            float e[6], d[6];
            #pragma unroll
            for (int cc = 0; cc < 6; ++cc) {
                float la = sP[base + cc];
                float lb = sP[base + SPITCH + cc];
                float lc = sP[base + 2 * SPITCH + cc];
                e[cc] = fmaf(2.0f, lb, la + lc);   // vertical [1,2,1]
                d[cc] = lc - la;                   // vertical [-1,0,1]
            }
            #pragma unroll
            for (int jj = 0; jj < 4; ++jj) {
                if (jj < sncols) {
                    float Ix = e[jj + 2] - e[jj];
                    float Iy = fmaf(2.0f, d[jj + 1], d[jj] + d[jj + 2]);
                    float It = second[jj] - o0[jj];
                    v0 = fmaf(Ix, Ix, v0);
                    v1 = fmaf(Iy, Iy, v1);
                    v2 = fmaf(Ix, Iy, v2);
                    v3 = fmaf(Ix, It, v3);
                    v4 = fmaf(Iy, It, v4);
                }
            }
        }

        // stage 1: warp reduce
        #pragma unroll
        for (int off = 16; off; off >>= 1) {
            v0 += __shfl_down_sync(0xffffffffu, v0, off);
            v1 += __shfl_down_sync(0xffffffffu, v1, off);
            v2 += __shfl_down_sync(0xffffffffu, v2, off);
            v3 += __shfl_down_sync(0xffffffffu, v3, off);
            v4 += __shfl_down_sync(0xffffffffu, v4, off);
        }
        if (lane == 0) {
            sRed[0][wid] = v0;
            sRed[1][wid] = v1;
            sRed[2][wid] = v2;
            sRed[3][wid] = v3;
            sRed[4][wid] = v4;
        }
        __syncthreads();                       // sync B: partials visible

        // stage 2: vectorized broadcast reads; every thread solves locally
        float4 q0 = *(const float4*)(&sRed[0][0]);
        float4 q1 = *(const float4*)(&sRed[1][0]);
        float4 q2 = *(const float4*)(&sRed[2][0]);
        float4 q3 = *(const float4*)(&sRed[3][0]);
        float4 q4 = *(const float4*)(&sRed[4][0]);
        float Ix2  = (q0.x + q0.y) + (q0.z + q0.w);
        float Iy2  = (q1.x + q1.y) + (q1.z + q1.w);
        float IxIy = (q2.x + q2.y) + (q2.z + q2.w);
        float IxIt = (q3.x + q3.y) + (q3.z + q3.w);
        float IyIt = (q4.x + q4.y) + (q4.z + q4.w);

        float det_inv = 1.0f / (Ix2 * Iy2 - IxIy * IxIy);
        float Vx = det_inv * (Iy2    * (-IxIt) + (-IxIy) * (-IyIt));
        float Vy = det_inv * ((-IxIy) * (-IxIt) + Ix2    * (-IyIt));
        sx = sx - Vx;
        sy = sy - Vy;
    }

    // final sample of frame 0 at converged positions (direct gathers, once)
    if (act) {
        float o0[4];
        sample4G(f0, sx, sy, o0);
        float* o0p = out + ((((size_t)b * 2) + 0) * NT + t) * PP + si * WHD + sj0;
        #pragma unroll
        for (int jj = 0; jj < 4; ++jj)
            if (jj < sncols) o0p[jj] = o0[jj];
    }
}

extern "C" void kernel_launch(void* const* d_in, const int* in_sizes, int n_in,
                              void* d_out, int out_size)
{
    // track_locs: 8*512 = 4096 floats; imgs: 8*2*1024*1024 floats.
    const float* track;
    const float* imgs;
    if (in_sizes[0] < in_sizes[1]) {
        track = (const float*)d_in[0];
        imgs  = (const float*)d_in[1];
    } else {
        track = (const float*)d_in[1];
        imgs  = (const float*)d_in[0];
    }
    float* out = (float*)d_out;
    mt_kernel<<<BB * NT, NTHREADS>>>(track, imgs, out);
}

// round 8
// speedup vs baseline: 1.2364x; 1.1481x over previous
#include <cuda_runtime.h>

// Problem constants (fixed by the reference)
#define BB 8
#define NT 256
#define WHD 21
#define PP 441          // WHD*WHD
#define SPITCH 23       // padded patch pitch
#define SPSZ (SPITCH * 23 + 8)   // +8 zero slack for row-chunk over-read at sc==5
#define IMW 1024
#define ITERS 20
#define NTHREADS 128
#define NWARPS 4
#define PTS 4           // patch points per thread in sample mapping

__global__ __launch_bounds__(NTHREADS, 14)
void mt_kernel(const float* __restrict__ track,
               const float* __restrict__ imgs,
               float* __restrict__ out)
{
    const int id = blockIdx.x;           // 0 .. B*NT-1
    const int b = id >> 8;               // id / NT (NT = 256)
    const int t = id & 255;

    const float* f0 = imgs + (size_t)b * 2 * IMW * IMW;   // frame 0 (H==W==1024)
    const float* f1 = f0 + (size_t)(IMW * IMW);           // frame 1

    __shared__ float sP[SPSZ];                       // zero-padded sampled patch
    __shared__ float sIt[PP + 8];                    // It = second - o0 (p-layout)
    __shared__ __align__(16) float sRed[5][NWARPS];  // per-warp partial sums

    const int tid  = threadIdx.x;
    const int lane = tid & 31;
    const int wid  = tid >> 5;

    // stencil mapping: thread = (patch row si, 4-col chunk sc); 126 active
    const int si   = tid / 6;
    const int sc   = tid - si * 6;
    const int sj0  = sc * 4;
    const bool sact = (si < WHD);
    const int sncols = (sc == 5) ? 1 : 4;            // col 20 only in last chunk

    // per-thread shift state (all threads compute identically)
    float sx, sy;
    {
        const float SCALE = 21.0f / 1024.0f;   // exact in fp32
        sx = track[b * (NT * 2) + t * 2 + 0] / SCALE;
        sy = track[b * (NT * 2) + t * 2 + 1] / SCALE;
    }

    // zero padded patch (+slack); border & slack stay zero forever
    #pragma unroll
    for (int k = tid; k < SPSZ; k += NTHREADS) sP[k] = 0.0f;

    // direct-gather bilinear, exact reference clip-then-weight (R3-proven)
    auto bilinearG = [&](const float* __restrict__ f, float gx, float gy,
                         float ssx, float ssy) -> float {
        float x = (gx + ssx) * 10.5f;    // WH*0.5
        float y = (gy + ssy) * 10.5f;
        float fx = floorf(x);
        float fy = floorf(y);
        float x0 = fminf(fmaxf(fx,        0.0f), 1023.0f);
        float x1 = fminf(fmaxf(fx + 1.0f, 0.0f), 1023.0f);
        float y0 = fminf(fmaxf(fy,        0.0f), 1023.0f);
        float y1 = fminf(fmaxf(fy + 1.0f, 0.0f), 1023.0f);
        float wa = (y1 - y) * (x1 - x);
        float wb = (y1 - y) * (x  - x0);
        float wc = (y  - y0) * (x1 - x);
        float wd = (y  - y0) * (x  - x0);
        int xi0 = (int)x0, xi1 = (int)x1;
        int yi0 = (int)y0, yi1 = (int)y1;
        const float* r0 = f + yi0 * IMW;
        const float* r1 = f + yi1 * IMW;
        return wa * __ldg(r0 + xi0) + wb * __ldg(r0 + xi1)
             + wc * __ldg(r1 + xi0) + wd * __ldg(r1 + xi1);
    };

    // 'second' (frame 1 at initial positions) — fixed for all iterations
    float second[PTS];
    {
        int i = tid / WHD;
        int j = tid - i * WHD;
        float* o1 = out + ((((size_t)b * 2) + 1) * NT + t) * PP;
        #pragma unroll
        for (int k = 0; k < PTS; ++k) {
            second[k] = 0.0f;
            if (i < WHD) {
                const float gx = -1.0f + 0.1f * (float)j;
                const float gy = -1.0f + 0.1f * (float)i;
                second[k] = bilinearG(f1, gx, gy, sx, sy);
                o1[tid + k * NTHREADS] = second[k];
            }
            j += 2; i += 6; if (j >= WHD) { j -= WHD; ++i; }   // p += 128
        }
    }

    __syncthreads();   // padded border zeros visible

    for (int it = 0; it < ITERS; ++it) {
        // ---- sample f0 directly (p-mapping, coalesced-ish L1-cached gathers) ----
        {
            int i = tid / WHD;
            int j = tid - i * WHD;
            #pragma unroll
            for (int k = 0; k < PTS; ++k) {
                if (i < WHD) {
                    const float gx = -1.0f + 0.1f * (float)j;
                    const float gy = -1.0f + 0.1f * (float)i;
                    float o0 = bilinearG(f0, gx, gy, sx, sy);
                    sP[(i + 1) * SPITCH + (j + 1)] = o0;
                    sIt[tid + k * NTHREADS] = second[k] - o0;   // It in p-layout
                }
                j += 2; i += 6; if (j >= WHD) { j -= WHD; ++i; }
            }
        }
        __syncthreads();                       // sync A: patch + It visible

        // ---- row-chunk Sobel stencil + local accumulation ----
        float v0 = 0.f, v1 = 0.f, v2 = 0.f, v3 = 0.f, v4 = 0.f;
        if (sact) {
            const int base = si * SPITCH + sj0;
            float e[6], d[6];
            #pragma unroll
            for (int cc = 0; cc < 6; ++cc) {
                float la = sP[base + cc];
                float lb = sP[base + SPITCH + cc];
                float lc = sP[base + 2 * SPITCH + cc];
                e[cc] = fmaf(2.0f, lb, la + lc);   // vertical [1,2,1]
                d[cc] = lc - la;                   // vertical [-1,0,1]
            }
            const int itb = si * WHD + sj0;
            #pragma unroll
            for (int jj = 0; jj < 4; ++jj) {
                if (jj < sncols) {
                    float Ix = e[jj + 2] - e[jj];
                    float Iy = fmaf(2.0f, d[jj + 1], d[jj] + d[jj + 2]);
                    float It = sIt[itb + jj];
                    v0 = fmaf(Ix, Ix, v0);
                    v1 = fmaf(Iy, Iy, v1);
                    v2 = fmaf(Ix, Iy, v2);
                    v3 = fmaf(Ix, It, v3);
                    v4 = fmaf(Iy, It, v4);
                }
            }
        }

        // stage 1: warp reduce
        #pragma unroll
        for (int off = 16; off; off >>= 1) {
            v0 += __shfl_down_sync(0xffffffffu, v0, off);
            v1 += __shfl_down_sync(0xffffffffu, v1, off);
            v2 += __shfl_down_sync(0xffffffffu, v2, off);
            v3 += __shfl_down_sync(0xffffffffu, v3, off);
            v4 += __shfl_down_sync(0xffffffffu, v4, off);
        }
        if (lane == 0) {
            sRed[0][wid] = v0;
            sRed[1][wid] = v1;
            sRed[2][wid] = v2;
            sRed[3][wid] = v3;
            sRed[4][wid] = v4;
        }
        __syncthreads();                       // sync B: partials visible
                                               // (also fences sP/sIt reuse)

        // stage 2: vectorized broadcast reads; every thread solves locally
        float4 q0 = *(const float4*)(&sRed[0][0]);
        float4 q1 = *(const float4*)(&sRed[1][0]);
        float4 q2 = *(const float4*)(&sRed[2][0]);
        float4 q3 = *(const float4*)(&sRed[3][0]);
        float4 q4 = *(const float4*)(&sRed[4][0]);
        float Ix2  = (q0.x + q0.y) + (q0.z + q0.w);
        float Iy2  = (q1.x + q1.y) + (q1.z + q1.w);
        float IxIy = (q2.x + q2.y) + (q2.z + q2.w);
        float IxIt = (q3.x + q3.y) + (q3.z + q3.w);
        float IyIt = (q4.x + q4.y) + (q4.z + q4.w);

        float det_inv = 1.0f / (Ix2 * Iy2 - IxIy * IxIy);
        float Vx = det_inv * (Iy2    * (-IxIt) + (-IxIy) * (-IyIt));
        float Vy = det_inv * ((-IxIy) * (-IxIt) + Ix2    * (-IyIt));
        sx = sx - Vx;
        sy = sy - Vy;
    }

    // final sample of frame 0 at converged positions
    {
        int i = tid / WHD;
        int j = tid - i * WHD;
        float* o0p = out + ((((size_t)b * 2) + 0) * NT + t) * PP;
        #pragma unroll
        for (int k = 0; k < PTS; ++k) {
            if (i < WHD) {
                const float gx = -1.0f + 0.1f * (float)j;
                const float gy = -1.0f + 0.1f * (float)i;
                o0p[tid + k * NTHREADS] = bilinearG(f0, gx, gy, sx, sy);
            }
            j += 2; i += 6; if (j >= WHD) { j -= WHD; ++i; }
        }
    }
}

extern "C" void kernel_launch(void* const* d_in, const int* in_sizes, int n_in,
                              void* d_out, int out_size)
{
    // track_locs: 8*512 = 4096 floats; imgs: 8*2*1024*1024 floats.
    const float* track;
    const float* imgs;
    if (in_sizes[0] < in_sizes[1]) {
        track = (const float*)d_in[0];
        imgs  = (const float*)d_in[1];
    } else {
        track = (const float*)d_in[1];
        imgs  = (const float*)d_in[0];
    }
    float* out = (float*)d_out;
    mt_kernel<<<BB * NT, NTHREADS>>>(track, imgs, out);
}

// round 9
// speedup vs baseline: 1.2410x; 1.0037x over previous
#include <cuda_runtime.h>

// Problem constants (fixed by the reference)
#define BB 8
#define NT 256
#define WHD 21
#define PP 441          // WHD*WHD
#define PAD 23          // zero-padded patch dim
#define IMH 1024
#define IMW 1024
#define ITERS 20
#define NTHREADS 128
#define NWARPS 4
#define PTS 4           // patch points per thread (4*128 = 512 >= 441)

__global__ __launch_bounds__(NTHREADS, 14)
void mt_kernel(const float* __restrict__ track,
               const float* __restrict__ imgs,
               float* __restrict__ out)
{
    const int id = blockIdx.x;           // 0 .. B*NT-1
    const int b = id >> 8;               // id / NT (NT = 256)
    const int t = id & 255;

    const float* f0 = imgs + (size_t)b * 2 * IMH * IMW;   // frame 0
    const float* f1 = f0 + (size_t)(IMH * IMW);           // frame 1

    __shared__ float sP[PAD * PAD];                  // zero-padded sampled patch
    __shared__ __align__(16) float sRed[5][NWARPS];  // per-warp partial sums

    const int tid  = threadIdx.x;
    const int lane = tid & 31;
    const int wid  = tid >> 5;

    // per-thread shift state (all threads compute identically)
    float sx, sy;
    {
        const float SCALE = 21.0f / 1024.0f;   // exact in fp32
        sx = track[b * (NT * 2) + t * 2 + 0] / SCALE;
        sy = track[b * (NT * 2) + t * 2 + 1] / SCALE;
    }

    // zero the padded patch once; border stays zero forever
    #pragma unroll
    for (int k = tid; k < PAD * PAD; k += NTHREADS) sP[k] = 0.0f;

    // exact replication of the reference bilinear (clip indices, then weights)
    auto bilinear = [&](const float* __restrict__ f, float gx, float gy,
                        float ssx, float ssy) -> float {
        float x = (gx + ssx) * 10.5f;    // WH*0.5
        float y = (gy + ssy) * 10.5f;
        float fx = floorf(x);
        float fy = floorf(y);
        float x0 = fminf(fmaxf(fx,        0.0f), 1023.0f);
        float x1 = fminf(fmaxf(fx + 1.0f, 0.0f), 1023.0f);
        float y0 = fminf(fmaxf(fy,        0.0f), 1023.0f);
        float y1 = fminf(fmaxf(fy + 1.0f, 0.0f), 1023.0f);
        float wa = (y1 - y) * (x1 - x);
        float wb = (y1 - y) * (x  - x0);
        float wc = (y  - y0) * (x1 - x);
        float wd = (y  - y0) * (x  - x0);
        int xi0 = (int)x0, xi1 = (int)x1;
        int yi0 = (int)y0, yi1 = (int)y1;
        const float* r0 = f + yi0 * IMW;
        const float* r1 = f + yi1 * IMW;
        return wa * __ldg(r0 + xi0) + wb * __ldg(r0 + xi1)
             + wc * __ldg(r1 + xi0) + wd * __ldg(r1 + xi1);
    };

    // 'second' (frame 1 at initial positions) — fixed for all iterations
    float second[PTS];
    #pragma unroll
    for (int k = 0; k < PTS; ++k) {
        const int p = tid + k * NTHREADS;
        second[k] = 0.0f;
        if (p < PP) {
            const int i = p / WHD;
            const int j = p - i * WHD;
            const float gx = -1.0f + 0.1f * (float)j;
            const float gy = -1.0f + 0.1f * (float)i;
            second[k] = bilinear(f1, gx, gy, sx, sy);
            out[((((size_t)b * 2) + 1) * NT + t) * PP + p] = second[k];
        }
    }

    __syncthreads();   // padded border zeros visible

    for (int it = 0; it < ITERS; ++it) {
        float o0[PTS];
        #pragma unroll
        for (int k = 0; k < PTS; ++k) {
            const int p = tid + k * NTHREADS;
            if (p < PP) {
                const int i = p / WHD;
                const int j = p - i * WHD;
                const float gx = -1.0f + 0.1f * (float)j;
                const float gy = -1.0f + 0.1f * (float)i;
                o0[k] = bilinear(f0, gx, gy, sx, sy);
                sP[(i + 1) * PAD + (j + 1)] = o0[k];
            }
        }
        __syncthreads();                       // sync A: patch visible

        float v0 = 0.f, v1 = 0.f, v2 = 0.f, v3 = 0.f, v4 = 0.f;
        #pragma unroll
        for (int k = 0; k < PTS; ++k) {
            const int p = tid + k * NTHREADS;
            if (p < PP) {
                const int i = p / WHD;
                const int j = p - i * WHD;
                const int pb = (i + 1) * PAD + (j + 1);
                // unconditional zero-padded 3x3 stencil (cross-corr., matches lax.conv)
                float a00 = sP[pb - PAD - 1], a01 = sP[pb - PAD], a02 = sP[pb - PAD + 1];
                float a10 = sP[pb - 1],                            a12 = sP[pb + 1];
                float a20 = sP[pb + PAD - 1], a21 = sP[pb + PAD], a22 = sP[pb + PAD + 1];
                float Ix = (a02 - a00) + 2.0f * (a12 - a10) + (a22 - a20);
                float Iy = (a20 - a00) + 2.0f * (a21 - a01) + (a22 - a02);
                float It = second[k] - o0[k];
                v0 += Ix * Ix;
                v1 += Iy * Iy;
                v2 += Ix * Iy;
                v3 += Ix * It;
                v4 += Iy * It;
            }
        }

        // stage 1: warp reduce (sum lands in lane 0)
        #pragma unroll
        for (int off = 16; off; off >>= 1) {
            v0 += __shfl_down_sync(0xffffffffu, v0, off);
            v1 += __shfl_down_sync(0xffffffffu, v1, off);
            v2 += __shfl_down_sync(0xffffffffu, v2, off);
            v3 += __shfl_down_sync(0xffffffffu, v3, off);
            v4 += __shfl_down_sync(0xffffffffu, v4, off);
        }
        if (lane == 0) {
            sRed[0][wid] = v0;
            sRed[1][wid] = v1;
            sRed[2][wid] = v2;
            sRed[3][wid] = v3;
            sRed[4][wid] = v4;
        }
        __syncthreads();                       // sync B: partials visible

        // stage 2: vectorized broadcast reads; every thread solves locally
        float4 q0 = *(const float4*)(&sRed[0][0]);
        float4 q1 = *(const float4*)(&sRed[1][0]);
        float4 q2 = *(const float4*)(&sRed[2][0]);
        float4 q3 = *(const float4*)(&sRed[3][0]);
        float4 q4 = *(const float4*)(&sRed[4][0]);
        float Ix2  = (q0.x + q0.y) + (q0.z + q0.w);
        float Iy2  = (q1.x + q1.y) + (q1.z + q1.w);
        float IxIy = (q2.x + q2.y) + (q2.z + q2.w);
        float IxIt = (q3.x + q3.y) + (q3.z + q3.w);
        float IyIt = (q4.x + q4.y) + (q4.z + q4.w);

        float det_inv = 1.0f / (Ix2 * Iy2 - IxIy * IxIy);
        float Vx = det_inv * (Iy2    * (-IxIt) + (-IxIy) * (-IyIt));
        float Vy = det_inv * ((-IxIy) * (-IxIt) + Ix2    * (-IyIt));
        sx = sx - Vx;
        sy = sy - Vy;
    }

    // final sample of frame 0 at converged positions
    #pragma unroll
    for (int k = 0; k < PTS; ++k) {
        const int p = tid + k * NTHREADS;
        if (p < PP) {
            const int i = p / WHD;
            const int j = p - i * WHD;
            const float gx = -1.0f + 0.1f * (float)j;
            const float gy = -1.0f + 0.1f * (float)i;
            float o0 = bilinear(f0, gx, gy, sx, sy);
            out[((((size_t)b * 2) + 0) * NT + t) * PP + p] = o0;
        }
    }
}

extern "C" void kernel_launch(void* const* d_in, const int* in_sizes, int n_in,
                              void* d_out, int out_size)
{
    // track_locs: 8*512 = 4096 floats; imgs: 8*2*1024*1024 floats.
    const float* track;
    const float* imgs;
    if (in_sizes[0] < in_sizes[1]) {
        track = (const float*)d_in[0];
        imgs  = (const float*)d_in[1];
    } else {
        track = (const float*)d_in[1];
        imgs  = (const float*)d_in[0];
    }
    float* out = (float*)d_out;
    mt_kernel<<<BB * NT, NTHREADS>>>(track, imgs, out);
}

// round 10
// speedup vs baseline: 1.5468x; 1.2464x over previous
#include <cuda_runtime.h>

// Problem constants (fixed by the reference)
#define BB 8
#define NT 256
#define WHD 21
#define PP 441          // WHD*WHD
#define PAD 23          // zero-padded patch dim
#define IMW 1024
#define ITERS 20
#define PTS 14          // points per lane: 32*14 = 448 >= 441

__global__ __launch_bounds__(32)
void mt_kernel(const float* __restrict__ track,
               const float* __restrict__ imgs,
               float* __restrict__ out)
{
    const int id = blockIdx.x;           // 0 .. B*NT-1, one warp per track
    const int b = id >> 8;               // id / NT (NT = 256)
    const int t = id & 255;

    const float* f0 = imgs + (size_t)b * 2 * IMW * IMW;   // frame 0 (H==W==1024)
    const float* f1 = f0 + (size_t)(IMW * IMW);           // frame 1

    __shared__ float sP[PAD * PAD];      // zero-padded sampled patch (warp-private)

    const int lane = threadIdx.x;

    // per-lane shift state (uniform across the warp)
    float sx, sy;
    {
        const float SCALE = 21.0f / 1024.0f;   // exact in fp32
        sx = track[b * (NT * 2) + t * 2 + 0] / SCALE;
        sy = track[b * (NT * 2) + t * 2 + 1] / SCALE;
    }

    // zero the padded patch once; border stays zero forever
    #pragma unroll
    for (int k = lane; k < PAD * PAD; k += 32) sP[k] = 0.0f;

    // exact replication of the reference bilinear (clip indices, then weights)
    auto bilinear = [&](const float* __restrict__ f, float gx, float gy,
                        float ssx, float ssy) -> float {
        float x = (gx + ssx) * 10.5f;    // WH*0.5
        float y = (gy + ssy) * 10.5f;
        float fx = floorf(x);
        float fy = floorf(y);
        float x0 = fminf(fmaxf(fx,        0.0f), 1023.0f);
        float x1 = fminf(fmaxf(fx + 1.0f, 0.0f), 1023.0f);
        float y0 = fminf(fmaxf(fy,        0.0f), 1023.0f);
        float y1 = fminf(fmaxf(fy + 1.0f, 0.0f), 1023.0f);
        float wa = (y1 - y) * (x1 - x);
        float wb = (y1 - y) * (x  - x0);
        float wc = (y  - y0) * (x1 - x);
        float wd = (y  - y0) * (x  - x0);
        int xi0 = (int)x0, xi1 = (int)x1;
        int yi0 = (int)y0, yi1 = (int)y1;
        const float* r0 = f + yi0 * IMW;
        const float* r1 = f + yi1 * IMW;
        return wa * __ldg(r0 + xi0) + wb * __ldg(r0 + xi1)
             + wc * __ldg(r1 + xi0) + wd * __ldg(r1 + xi1);
    };

    // 'second' (frame 1 at initial positions) — fixed for all iterations
    float second[PTS];
    #pragma unroll
    for (int k = 0; k < PTS; ++k) {
        const int p = lane + k * 32;
        second[k] = 0.0f;
        if (p < PP) {
            const int i = p / WHD;
            const int j = p - i * WHD;
            const float gx = -1.0f + 0.1f * (float)j;
            const float gy = -1.0f + 0.1f * (float)i;
            second[k] = bilinear(f1, gx, gy, sx, sy);
            out[((((size_t)b * 2) + 1) * NT + t) * PP + p] = second[k];
        }
    }

    for (int it = 0; it < ITERS; ++it) {
        // ---- sample f0 (lane-consecutive points -> coalesced L1 gathers) ----
        float o0[PTS];
        #pragma unroll
        for (int k = 0; k < PTS; ++k) {
            const int p = lane + k * 32;
            if (p < PP) {
                const int i = p / WHD;
                const int j = p - i * WHD;
                const float gx = -1.0f + 0.1f * (float)j;
                const float gy = -1.0f + 0.1f * (float)i;
                o0[k] = bilinear(f0, gx, gy, sx, sy);
                sP[(i + 1) * PAD + (j + 1)] = o0[k];
            }
        }
        __syncwarp();                    // patch writes visible to stencil reads

        // ---- per-point zero-padded Sobel stencil + local accumulation ----
        float v0 = 0.f, v1 = 0.f, v2 = 0.f, v3 = 0.f, v4 = 0.f;
        #pragma unroll
        for (int k = 0; k < PTS; ++k) {
            const int p = lane + k * 32;
            if (p < PP) {
                const int i = p / WHD;
                const int j = p - i * WHD;
                const int pb = (i + 1) * PAD + (j + 1);
                float a00 = sP[pb - PAD - 1], a01 = sP[pb - PAD], a02 = sP[pb - PAD + 1];
                float a10 = sP[pb - 1],                            a12 = sP[pb + 1];
                float a20 = sP[pb + PAD - 1], a21 = sP[pb + PAD], a22 = sP[pb + PAD + 1];
                float Ix = (a02 - a00) + 2.0f * (a12 - a10) + (a22 - a20);
                float Iy = (a20 - a00) + 2.0f * (a21 - a01) + (a22 - a02);
                float It = second[k] - o0[k];
                v0 = fmaf(Ix, Ix, v0);
                v1 = fmaf(Iy, Iy, v1);
                v2 = fmaf(Ix, Iy, v2);
                v3 = fmaf(Ix, It, v3);
                v4 = fmaf(Iy, It, v4);
            }
        }

        // ---- butterfly reduction: every lane ends with the full sums ----
        // (also acts as the convergence point: all stencil reads are consumed
        //  via the v* data dependency before any lane proceeds to next iter)
        #pragma unroll
        for (int off = 16; off; off >>= 1) {
            v0 += __shfl_xor_sync(0xffffffffu, v0, off);
            v1 += __shfl_xor_sync(0xffffffffu, v1, off);
            v2 += __shfl_xor_sync(0xffffffffu, v2, off);
            v3 += __shfl_xor_sync(0xffffffffu, v3, off);
            v4 += __shfl_xor_sync(0xffffffffu, v4, off);
        }

        // ---- 2x2 solve (every lane, identical) ----
        float det_inv = 1.0f / (v0 * v1 - v2 * v2);
        float Vx = det_inv * (v1    * (-v3) + (-v2) * (-v4));
        float Vy = det_inv * ((-v2) * (-v3) + v0    * (-v4));
        sx = sx - Vx;
        sy = sy - Vy;
    }

    // final sample of frame 0 at converged positions
    #pragma unroll
    for (int k = 0; k < PTS; ++k) {
        const int p = lane + k * 32;
        if (p < PP) {
            const int i = p / WHD;
            const int j = p - i * WHD;
            const float gx = -1.0f + 0.1f * (float)j;
            const float gy = -1.0f + 0.1f * (float)i;
            float o0 = bilinear(f0, gx, gy, sx, sy);
            out[((((size_t)b * 2) + 0) * NT + t) * PP + p] = o0;
        }
    }
}

extern "C" void kernel_launch(void* const* d_in, const int* in_sizes, int n_in,
                              void* d_out, int out_size)
{
    // track_locs: 8*512 = 4096 floats; imgs: 8*2*1024*1024 floats.
    const float* track;
    const float* imgs;
    if (in_sizes[0] < in_sizes[1]) {
        track = (const float*)d_in[0];
        imgs  = (const float*)d_in[1];
    } else {
        track = (const float*)d_in[1];
        imgs  = (const float*)d_in[0];
    }
    float* out = (float*)d_out;
    mt_kernel<<<BB * NT, 32>>>(track, imgs, out);
}